// round 3
// baseline (speedup 1.0000x reference)
#include <cuda_runtime.h>
#include <math.h>

// ---------------------------------------------------------------------------
// CausalSelfAttention, TF32 mma.sync, packed-pair smem layouts (LDS.64 frags)
// ---------------------------------------------------------------------------

#define BATCH 2
#define SEQ   4096
#define DMODEL 512
#define NHEADS 8
#define HDIM  64
#define ROWS  (BATCH * SEQ)
#define QKVCOLS (3 * DMODEL)

static __device__ float g_qkv[ROWS * QKVCOLS];
static __device__ float g_attn[ROWS * DMODEL];

__device__ __forceinline__ unsigned f2tf(float x) {
    unsigned r;
    asm("cvt.rna.tf32.f32 %0, %1;" : "=r"(r) : "f"(x));
    return r;
}

__device__ __forceinline__ void mma8(float* c,
                                     unsigned a0, unsigned a1, unsigned a2, unsigned a3,
                                     unsigned b0, unsigned b1) {
    asm("mma.sync.aligned.m16n8k8.row.col.f32.tf32.tf32.f32 "
        "{%0,%1,%2,%3}, {%4,%5,%6,%7}, {%8,%9}, {%0,%1,%2,%3};"
        : "+f"(c[0]), "+f"(c[1]), "+f"(c[2]), "+f"(c[3])
        : "r"(a0), "r"(a1), "r"(a2), "r"(a3), "r"(b0), "r"(b1));
}

// Pack 8 consecutive k-elements (two float4s) as interleaved pairs
// (e0,e4, e1,e5, e2,e6, e3,e7) so fragment pair j = one uint2 at offset 2j.
__device__ __forceinline__ void pack8(unsigned* rowp, int d0,
                                      float4 a, float4 b, float s) {
    *(uint4*)(rowp + d0) = make_uint4(f2tf(a.x * s), f2tf(b.x * s),
                                      f2tf(a.y * s), f2tf(b.y * s));
    *(uint4*)(rowp + d0 + 4) = make_uint4(f2tf(a.z * s), f2tf(b.z * s),
                                          f2tf(a.w * s), f2tf(b.w * s));
}

// ---------------------------------------------------------------------------
// TF32 GEMM: C[M,N] = A[M,K] @ B[N,K]^T. Block 128x128, 256 threads (8 warps),
// warp tile 64x32, BK=32, packed-pair smem (pitch 40 -> conflict-free LDS.64).
// ---------------------------------------------------------------------------
#define GPP 40

__global__ __launch_bounds__(256, 2)
void gemm_tf32(const float* __restrict__ A, const float* __restrict__ B,
               float* __restrict__ C, int K, int N)
{
    __shared__ unsigned As[128 * GPP];
    __shared__ unsigned Bs[128 * GPP];

    const int tid  = threadIdx.x;
    const int lane = tid & 31;
    const int wid  = tid >> 5;
    const int g    = lane >> 2;
    const int cc   = lane & 3;
    const int wm   = (wid & 1) * 64;
    const int wn   = (wid >> 1) * 32;
    const int m0   = blockIdx.y * 128;
    const int n0   = blockIdx.x * 128;

    float acc[4][4][4] = {};

    const int sr = tid >> 1;            // staging row 0..127
    const int sd = (tid & 1) * 16;      // staging k-offset 0/16

    for (int k0 = 0; k0 < K; k0 += 32) {
        __syncthreads();
        {
            const float* ap = A + (size_t)(m0 + sr) * K + k0 + sd;
            pack8(&As[sr * GPP], sd,     *(const float4*)ap,       *(const float4*)(ap + 4),  1.f);
            pack8(&As[sr * GPP], sd + 8, *(const float4*)(ap + 8), *(const float4*)(ap + 12), 1.f);
            const float* bp = B + (size_t)(n0 + sr) * K + k0 + sd;
            pack8(&Bs[sr * GPP], sd,     *(const float4*)bp,       *(const float4*)(bp + 4),  1.f);
            pack8(&Bs[sr * GPP], sd + 8, *(const float4*)(bp + 8), *(const float4*)(bp + 12), 1.f);
        }
        __syncthreads();

        #pragma unroll
        for (int ks = 0; ks < 4; ks++) {
            uint2 a02[4], a13[4];
            #pragma unroll
            for (int mt = 0; mt < 4; mt++) {
                a02[mt] = ((const uint2*)&As[(wm + mt * 16 + g) * GPP + ks * 8])[cc];
                a13[mt] = ((const uint2*)&As[(wm + mt * 16 + g + 8) * GPP + ks * 8])[cc];
            }
            #pragma unroll
            for (int nt = 0; nt < 4; nt++) {
                uint2 bb = ((const uint2*)&Bs[(wn + nt * 8 + g) * GPP + ks * 8])[cc];
                #pragma unroll
                for (int mt = 0; mt < 4; mt++)
                    mma8(acc[mt][nt], a02[mt].x, a13[mt].x, a02[mt].y, a13[mt].y,
                         bb.x, bb.y);
            }
        }
    }

    #pragma unroll
    for (int mt = 0; mt < 4; mt++) {
        int row = m0 + wm + mt * 16 + g;
        #pragma unroll
        for (int nt = 0; nt < 4; nt++) {
            int col = n0 + wn + nt * 8 + 2 * cc;
            *(float2*)&C[(size_t)row * N + col] =
                make_float2(acc[mt][nt][0], acc[mt][nt][1]);
            *(float2*)&C[(size_t)(row + 8) * N + col] =
                make_float2(acc[mt][nt][2], acc[mt][nt][3]);
        }
    }
}

// ---------------------------------------------------------------------------
// TF32 flash attention, causal. 256 threads (8 warps), q-tile 128, kv-tile 64.
// Packed-pair smem (pitch 72): Qp[128], Kp[64], Vp[64] (k-transposed), Pp[128].
// Warp tile: 16 q-rows x 64 kv-cols. All fragment loads = conflict-free LDS.64.
// ---------------------------------------------------------------------------
#define AP 72
#define ASMEM ((128 * AP + 64 * AP + 64 * AP + 128 * AP) * 4)

__global__ __launch_bounds__(256, 2)
void flash_tf32(const float* __restrict__ qkv, float* __restrict__ out)
{
    extern __shared__ unsigned sm[];
    unsigned* Qp = sm;                  // 128 x AP
    unsigned* Kp = Qp + 128 * AP;       // 64 x AP
    unsigned* Vp = Kp + 64 * AP;        // 64 x AP, k-transposed packing
    unsigned* Pp = Vp + 64 * AP;        // 128 x AP

    const int tid  = threadIdx.x;
    const int lane = tid & 31;
    const int w    = tid >> 5;
    const int g    = lane >> 2;
    const int cc   = lane & 3;
    const int qt   = (int)gridDim.x - 1 - (int)blockIdx.x;  // heavy tiles first
    const int b    = blockIdx.y >> 3;
    const int h    = blockIdx.y & 7;
    const int q0   = qt * 128;
    const int wrow = w * 16;
    const size_t base = (size_t)b * SEQ * QKVCOLS + (size_t)h * HDIM;

    // ---- stage Q tile (scaled by 1/8, tf32) ----
    {
        const int r  = tid >> 1;
        const int d0 = (tid & 1) * 32;
        const float* src = qkv + base + (size_t)(q0 + r) * QKVCOLS + d0;
        #pragma unroll
        for (int e = 0; e < 4; e++)
            pack8(&Qp[r * AP], d0 + e * 8,
                  *(const float4*)(src + e * 8), *(const float4*)(src + e * 8 + 4),
                  0.125f);
    }

    float rmax[2] = {-1e30f, -1e30f};
    float rsum[2] = {0.f, 0.f};
    float o[8][4] = {};

    const int ntk = 2 * qt + 2;
    for (int kt = 0; kt < ntk; kt++) {
        const int k0 = kt * 64;
        __syncthreads();  // previous Kp/Vp fully consumed

        // ---- stage K (row-packed) and V (k-transposed packed) ----
        {
            const int r  = tid >> 2;            // kv row 0..63
            const int d0 = (tid & 3) * 16;
            const float* kp = qkv + base + (size_t)(k0 + r) * QKVCOLS + DMODEL + d0;
            pack8(&Kp[r * AP], d0,     *(const float4*)kp,       *(const float4*)(kp + 4),  1.f);
            pack8(&Kp[r * AP], d0 + 8, *(const float4*)(kp + 8), *(const float4*)(kp + 12), 1.f);

            const float* vsrc = kp + DMODEL;
            const int pk = ((r >> 3) << 3) + ((r & 3) << 1) + ((r >> 2) & 1);
            #pragma unroll
            for (int e = 0; e < 4; e++) {
                float4 vv = *(const float4*)(vsrc + e * 4);
                unsigned* dst = &Vp[(d0 + e * 4) * AP + pk];
                dst[0]      = f2tf(vv.x);
                dst[AP]     = f2tf(vv.y);
                dst[2 * AP] = f2tf(vv.z);
                dst[3 * AP] = f2tf(vv.w);
            }
        }
        __syncthreads();

        // warps whose rows are entirely below this kv tile skip it
        if (k0 > q0 + wrow + 15) continue;

        // ---- S = Q @ K^T ----
        float s[8][4] = {};
        #pragma unroll
        for (int ks = 0; ks < 8; ks++) {
            uint2 A02 = ((const uint2*)&Qp[(wrow + g) * AP + ks * 8])[cc];
            uint2 A13 = ((const uint2*)&Qp[(wrow + g + 8) * AP + ks * 8])[cc];
            #pragma unroll
            for (int nt = 0; nt < 8; nt++) {
                uint2 B01 = ((const uint2*)&Kp[(nt * 8 + g) * AP + ks * 8])[cc];
                mma8(s[nt], A02.x, A13.x, A02.y, A13.y, B01.x, B01.y);
            }
        }

        // ---- causal mask ----
        if (k0 + 63 > q0 + wrow) {
            const int r0 = q0 + wrow + g;
            const int r1 = r0 + 8;
            #pragma unroll
            for (int nt = 0; nt < 8; nt++) {
                int col = k0 + nt * 8 + 2 * cc;
                if (col     > r0) s[nt][0] = -1e30f;
                if (col + 1 > r0) s[nt][1] = -1e30f;
                if (col     > r1) s[nt][2] = -1e30f;
                if (col + 1 > r1) s[nt][3] = -1e30f;
            }
        }

        // ---- online softmax + packed P store ----
        const int u0 = ((2 * cc) & 3) * 2 + (cc >> 1);
        #pragma unroll
        for (int half = 0; half < 2; half++) {
            float mx = -1e30f;
            #pragma unroll
            for (int nt = 0; nt < 8; nt++)
                mx = fmaxf(mx, fmaxf(s[nt][half * 2], s[nt][half * 2 + 1]));
            mx = fmaxf(mx, __shfl_xor_sync(0xffffffffu, mx, 1));
            mx = fmaxf(mx, __shfl_xor_sync(0xffffffffu, mx, 2));
            const float nm   = fmaxf(rmax[half], mx);
            const float corr = __expf(rmax[half] - nm);
            rmax[half] = nm;

            float sum = 0.f;
            unsigned* pr = &Pp[(wrow + g + half * 8) * AP];
            #pragma unroll
            for (int nt = 0; nt < 8; nt++) {
                float p0 = __expf(s[nt][half * 2]     - nm);
                float p1 = __expf(s[nt][half * 2 + 1] - nm);
                sum += p0 + p1;
                pr[nt * 8 + u0]     = f2tf(p0);
                pr[nt * 8 + u0 + 2] = f2tf(p1);
                o[nt][half * 2]     *= corr;
                o[nt][half * 2 + 1] *= corr;
            }
            sum += __shfl_xor_sync(0xffffffffu, sum, 1);
            sum += __shfl_xor_sync(0xffffffffu, sum, 2);
            rsum[half] = rsum[half] * corr + sum;
        }
        __syncwarp();  // P region is warp-private

        // ---- O += P @ V ----
        #pragma unroll
        for (int ks = 0; ks < 8; ks++) {
            uint2 A02 = ((const uint2*)&Pp[(wrow + g) * AP + ks * 8])[cc];
            uint2 A13 = ((const uint2*)&Pp[(wrow + g + 8) * AP + ks * 8])[cc];
            #pragma unroll
            for (int nt = 0; nt < 8; nt++) {
                uint2 B01 = ((const uint2*)&Vp[(nt * 8 + g) * AP + ks * 8])[cc];
                mma8(o[nt], A02.x, A13.x, A02.y, A13.y, B01.x, B01.y);
            }
        }
    }

    // ---- epilogue ----
    const float inv0 = 1.f / rsum[0];
    const float inv1 = 1.f / rsum[1];
    const size_t orow = (size_t)b * SEQ + q0 + wrow + g;
    #pragma unroll
    for (int nt = 0; nt < 8; nt++) {
        size_t off = orow * DMODEL + h * HDIM + nt * 8 + 2 * cc;
        *(float2*)&out[off] = make_float2(o[nt][0] * inv0, o[nt][1] * inv0);
        *(float2*)&out[off + 8 * DMODEL] = make_float2(o[nt][2] * inv1, o[nt][3] * inv1);
    }
}

// ---------------------------------------------------------------------------
extern "C" void kernel_launch(void* const* d_in, const int* in_sizes, int n_in,
                              void* d_out, int out_size)
{
    const float* x    = (const float*)d_in[0];
    const float* wqkv = (const float*)d_in[1];
    const float* wo   = (const float*)d_in[2];
    float* out        = (float*)d_out;

    float *qkvp, *attnp;
    cudaGetSymbolAddress((void**)&qkvp, g_qkv);
    cudaGetSymbolAddress((void**)&attnp, g_attn);

    cudaFuncSetAttribute(flash_tf32,
                         cudaFuncAttributeMaxDynamicSharedMemorySize, ASMEM);

    // qkv = x @ W_QKV^T : M=8192, N=1536, K=512
    gemm_tf32<<<dim3(QKVCOLS / 128, ROWS / 128), 256>>>(x, wqkv, qkvp, DMODEL, QKVCOLS);

    // causal flash attention (q-tile 128)
    flash_tf32<<<dim3(SEQ / 128, BATCH * NHEADS), 256, ASMEM>>>(qkvp, attnp);

    // y = attn @ W_O^T : M=8192, N=512, K=512
    gemm_tf32<<<dim3(DMODEL / 128, ROWS / 128), 256>>>(attnp, wo, out, DMODEL, DMODEL);
}

// round 4
// speedup vs baseline: 1.0826x; 1.0826x over previous
#include <cuda_runtime.h>
#include <math.h>

// ---------------------------------------------------------------------------
// CausalSelfAttention, TF32 mma.sync.
// R2 structures (128-thread CTAs, 64x64 GEMM warp tile, q-tile 64, no reg
// caps) + packed-pair smem so every MMA fragment load is one LDS.64.
// ---------------------------------------------------------------------------

#define BATCH 2
#define SEQ   4096
#define DMODEL 512
#define NHEADS 8
#define HDIM  64
#define ROWS  (BATCH * SEQ)
#define QKVCOLS (3 * DMODEL)

static __device__ float g_qkv[ROWS * QKVCOLS];
static __device__ float g_attn[ROWS * DMODEL];

__device__ __forceinline__ unsigned f2tf(float x) {
    unsigned r;
    asm("cvt.rna.tf32.f32 %0, %1;" : "=r"(r) : "f"(x));
    return r;
}

__device__ __forceinline__ void mma8(float* c,
                                     unsigned a0, unsigned a1, unsigned a2, unsigned a3,
                                     unsigned b0, unsigned b1) {
    asm("mma.sync.aligned.m16n8k8.row.col.f32.tf32.tf32.f32 "
        "{%0,%1,%2,%3}, {%4,%5,%6,%7}, {%8,%9}, {%0,%1,%2,%3};"
        : "+f"(c[0]), "+f"(c[1]), "+f"(c[2]), "+f"(c[3])
        : "r"(a0), "r"(a1), "r"(a2), "r"(a3), "r"(b0), "r"(b1));
}

// Pack 8 consecutive k-elements as interleaved pairs (e0,e4,e1,e5,e2,e6,e3,e7)
// so the fragment pair (k=cc, k=cc+4) is one uint2 at index cc.
__device__ __forceinline__ void pack8(unsigned* rowp, int d0,
                                      float4 a, float4 b, float s) {
    *(uint4*)(rowp + d0) = make_uint4(f2tf(a.x * s), f2tf(b.x * s),
                                      f2tf(a.y * s), f2tf(b.y * s));
    *(uint4*)(rowp + d0 + 4) = make_uint4(f2tf(a.z * s), f2tf(b.z * s),
                                          f2tf(a.w * s), f2tf(b.w * s));
}

// ---------------------------------------------------------------------------
// TF32 GEMM: C[M,N] = A[M,K] @ B[N,K]^T. Block 128x128, 128 threads (4 warps),
// warp tile 64x64, BK=32, packed-pair smem pitch 40 (conflict-free LDS.64).
// ---------------------------------------------------------------------------
#define GPP 40

__global__ __launch_bounds__(128)
void gemm_tf32(const float* __restrict__ A, const float* __restrict__ B,
               float* __restrict__ C, int K, int N)
{
    __shared__ unsigned As[128 * GPP];
    __shared__ unsigned Bs[128 * GPP];

    const int tid  = threadIdx.x;
    const int lane = tid & 31;
    const int wid  = tid >> 5;
    const int g    = lane >> 2;
    const int cc   = lane & 3;
    const int wm   = (wid & 1) * 64;
    const int wn   = (wid >> 1) * 64;
    const int m0   = blockIdx.y * 128;
    const int n0   = blockIdx.x * 128;

    float acc[4][8][4] = {};

    for (int k0 = 0; k0 < K; k0 += 32) {
        __syncthreads();
        {   // each thread stages one full 32-k row of A and of B
            const float* ap = A + (size_t)(m0 + tid) * K + k0;
            const float* bp = B + (size_t)(n0 + tid) * K + k0;
            #pragma unroll
            for (int e = 0; e < 4; e++) {
                pack8(&As[tid * GPP], e * 8,
                      *(const float4*)(ap + e * 8), *(const float4*)(ap + e * 8 + 4), 1.f);
                pack8(&Bs[tid * GPP], e * 8,
                      *(const float4*)(bp + e * 8), *(const float4*)(bp + e * 8 + 4), 1.f);
            }
        }
        __syncthreads();

        #pragma unroll
        for (int ks = 0; ks < 4; ks++) {
            uint2 a02[4], a13[4], bb[8];
            #pragma unroll
            for (int mt = 0; mt < 4; mt++) {
                a02[mt] = ((const uint2*)&As[(wm + mt * 16 + g) * GPP + ks * 8])[cc];
                a13[mt] = ((const uint2*)&As[(wm + mt * 16 + g + 8) * GPP + ks * 8])[cc];
            }
            #pragma unroll
            for (int nt = 0; nt < 8; nt++)
                bb[nt] = ((const uint2*)&Bs[(wn + nt * 8 + g) * GPP + ks * 8])[cc];
            #pragma unroll
            for (int mt = 0; mt < 4; mt++)
                #pragma unroll
                for (int nt = 0; nt < 8; nt++)
                    mma8(acc[mt][nt], a02[mt].x, a13[mt].x, a02[mt].y, a13[mt].y,
                         bb[nt].x, bb[nt].y);
        }
    }

    #pragma unroll
    for (int mt = 0; mt < 4; mt++) {
        int row = m0 + wm + mt * 16 + g;
        #pragma unroll
        for (int nt = 0; nt < 8; nt++) {
            int col = n0 + wn + nt * 8 + 2 * cc;
            *(float2*)&C[(size_t)row * N + col] =
                make_float2(acc[mt][nt][0], acc[mt][nt][1]);
            *(float2*)&C[(size_t)(row + 8) * N + col] =
                make_float2(acc[mt][nt][2], acc[mt][nt][3]);
        }
    }
}

// ---------------------------------------------------------------------------
// TF32 flash attention, causal. 128 threads (4 warps), q-tile 64, kv-tile 64.
// Packed-pair smem pitch 72: Qp/Kp/Pp row-packed, Vp k-transposed-packed.
// Warp tile 16 q-rows x 64 kv-cols. All fragment loads = LDS.64, conflict-free.
// ---------------------------------------------------------------------------
#define AP 72
#define ASMEM (4 * 64 * AP * 4)

__global__ __launch_bounds__(128)
void flash_tf32(const float* __restrict__ qkv, float* __restrict__ out)
{
    extern __shared__ unsigned sm[];
    unsigned* Qp = sm;
    unsigned* Kp = Qp + 64 * AP;
    unsigned* Vp = Kp + 64 * AP;   // k-transposed packed: Vp[d][pk(kv)]
    unsigned* Pp = Vp + 64 * AP;

    const int tid  = threadIdx.x;
    const int lane = tid & 31;
    const int w    = tid >> 5;
    const int g    = lane >> 2;
    const int cc   = lane & 3;
    const int qt   = (int)gridDim.x - 1 - (int)blockIdx.x;  // heavy tiles first
    const int b    = blockIdx.y >> 3;
    const int h    = blockIdx.y & 7;
    const int q0   = qt * 64;
    const int wrow = w * 16;
    const size_t base = (size_t)b * SEQ * QKVCOLS + (size_t)h * HDIM;

    // staging coords: lanes 0..63 rows, upper/lower 32 k-cols
    const int r  = tid & 63;
    const int d0 = (tid >> 6) * 32;
    // k-transposed pack position for V: pair-interleave within 8-row groups
    const int pk = ((r >> 3) << 3) + ((r & 3) << 1) + ((r >> 2) & 1);

    // ---- stage Q tile (scaled by 1/8) ----
    {
        const float* src = qkv + base + (size_t)(q0 + r) * QKVCOLS + d0;
        #pragma unroll
        for (int e = 0; e < 4; e++)
            pack8(&Qp[r * AP], d0 + e * 8,
                  *(const float4*)(src + e * 8), *(const float4*)(src + e * 8 + 4),
                  0.125f);
    }

    float rmax[2] = {-1e30f, -1e30f};
    float rsum[2] = {0.f, 0.f};
    float o[8][4] = {};

    const int ntk = qt + 1;
    for (int kt = 0; kt < ntk; kt++) {
        const int k0 = kt * 64;
        __syncthreads();   // previous Kp/Vp fully consumed

        // ---- stage K (row-packed) and V (k-transposed packed) ----
        {
            const float* kp = qkv + base + (size_t)(k0 + r) * QKVCOLS + DMODEL + d0;
            #pragma unroll
            for (int e = 0; e < 4; e++)
                pack8(&Kp[r * AP], d0 + e * 8,
                      *(const float4*)(kp + e * 8), *(const float4*)(kp + e * 8 + 4), 1.f);

            const float* vsrc = kp + DMODEL;
            #pragma unroll
            for (int e = 0; e < 8; e++) {
                float4 vv = *(const float4*)(vsrc + e * 4);
                unsigned* dst = &Vp[(d0 + e * 4) * AP + pk];
                dst[0]      = f2tf(vv.x);
                dst[AP]     = f2tf(vv.y);
                dst[2 * AP] = f2tf(vv.z);
                dst[3 * AP] = f2tf(vv.w);
            }
        }
        __syncthreads();

        // ---- S = Q @ K^T ----
        float s[8][4] = {};
        #pragma unroll
        for (int ks = 0; ks < 8; ks++) {
            uint2 A02 = ((const uint2*)&Qp[(wrow + g) * AP + ks * 8])[cc];
            uint2 A13 = ((const uint2*)&Qp[(wrow + g + 8) * AP + ks * 8])[cc];
            #pragma unroll
            for (int nt = 0; nt < 8; nt++) {
                uint2 B01 = ((const uint2*)&Kp[(nt * 8 + g) * AP + ks * 8])[cc];
                mma8(s[nt], A02.x, A13.x, A02.y, A13.y, B01.x, B01.y);
            }
        }

        // ---- causal mask (diagonal tile only) ----
        if (kt == ntk - 1) {
            const int r0 = q0 + wrow + g;
            const int r1 = r0 + 8;
            #pragma unroll
            for (int nt = 0; nt < 8; nt++) {
                int col = k0 + nt * 8 + 2 * cc;
                if (col     > r0) s[nt][0] = -1e30f;
                if (col + 1 > r0) s[nt][1] = -1e30f;
                if (col     > r1) s[nt][2] = -1e30f;
                if (col + 1 > r1) s[nt][3] = -1e30f;
            }
        }

        // ---- online softmax + packed P store ----
        const int u0 = ((2 * cc) & 3) * 2 + (cc >> 1);
        #pragma unroll
        for (int half = 0; half < 2; half++) {
            float mx = -1e30f;
            #pragma unroll
            for (int nt = 0; nt < 8; nt++)
                mx = fmaxf(mx, fmaxf(s[nt][half * 2], s[nt][half * 2 + 1]));
            mx = fmaxf(mx, __shfl_xor_sync(0xffffffffu, mx, 1));
            mx = fmaxf(mx, __shfl_xor_sync(0xffffffffu, mx, 2));
            const float nm   = fmaxf(rmax[half], mx);
            const float corr = __expf(rmax[half] - nm);
            rmax[half] = nm;

            float sum = 0.f;
            unsigned* pr = &Pp[(wrow + g + half * 8) * AP];
            #pragma unroll
            for (int nt = 0; nt < 8; nt++) {
                float p0 = __expf(s[nt][half * 2]     - nm);
                float p1 = __expf(s[nt][half * 2 + 1] - nm);
                sum += p0 + p1;
                pr[nt * 8 + u0]     = f2tf(p0);
                pr[nt * 8 + u0 + 2] = f2tf(p1);
                o[nt][half * 2]     *= corr;
                o[nt][half * 2 + 1] *= corr;
            }
            sum += __shfl_xor_sync(0xffffffffu, sum, 1);
            sum += __shfl_xor_sync(0xffffffffu, sum, 2);
            rsum[half] = rsum[half] * corr + sum;
        }
        __syncwarp();   // P region is warp-private

        // ---- O += P @ V ----
        #pragma unroll
        for (int ks = 0; ks < 8; ks++) {
            uint2 A02 = ((const uint2*)&Pp[(wrow + g) * AP + ks * 8])[cc];
            uint2 A13 = ((const uint2*)&Pp[(wrow + g + 8) * AP + ks * 8])[cc];
            #pragma unroll
            for (int nt = 0; nt < 8; nt++) {
                uint2 B01 = ((const uint2*)&Vp[(nt * 8 + g) * AP + ks * 8])[cc];
                mma8(o[nt], A02.x, A13.x, A02.y, A13.y, B01.x, B01.y);
            }
        }
    }

    // ---- epilogue ----
    const float inv0 = 1.f / rsum[0];
    const float inv1 = 1.f / rsum[1];
    const size_t orow = (size_t)b * SEQ + q0 + wrow + g;
    #pragma unroll
    for (int nt = 0; nt < 8; nt++) {
        size_t off = orow * DMODEL + h * HDIM + nt * 8 + 2 * cc;
        *(float2*)&out[off] = make_float2(o[nt][0] * inv0, o[nt][1] * inv0);
        *(float2*)&out[off + 8 * DMODEL] = make_float2(o[nt][2] * inv1, o[nt][3] * inv1);
    }
}

// ---------------------------------------------------------------------------
extern "C" void kernel_launch(void* const* d_in, const int* in_sizes, int n_in,
                              void* d_out, int out_size)
{
    const float* x    = (const float*)d_in[0];
    const float* wqkv = (const float*)d_in[1];
    const float* wo   = (const float*)d_in[2];
    float* out        = (float*)d_out;

    float *qkvp, *attnp;
    cudaGetSymbolAddress((void**)&qkvp, g_qkv);
    cudaGetSymbolAddress((void**)&attnp, g_attn);

    cudaFuncSetAttribute(flash_tf32,
                         cudaFuncAttributeMaxDynamicSharedMemorySize, ASMEM);

    // qkv = x @ W_QKV^T : M=8192, N=1536, K=512
    gemm_tf32<<<dim3(QKVCOLS / 128, ROWS / 128), 128>>>(x, wqkv, qkvp, DMODEL, QKVCOLS);

    // causal flash attention (q-tile 64)
    flash_tf32<<<dim3(SEQ / 64, BATCH * NHEADS), 128, ASMEM>>>(qkvp, attnp);

    // y = attn @ W_O^T : M=8192, N=512, K=512
    gemm_tf32<<<dim3(DMODEL / 128, ROWS / 128), 128>>>(attnp, wo, out, DMODEL, DMODEL);
}

// round 5
// speedup vs baseline: 1.6887x; 1.5598x over previous
#include <cuda_runtime.h>
#include <math.h>

// ---------------------------------------------------------------------------
// CausalSelfAttention via TF32 tensor-core mma.sync (sm_103a)
// R2 GEMMs verbatim (known-good); flash = R2 + double-buffered K/V prefetch.
// ---------------------------------------------------------------------------

#define BATCH 2
#define SEQ   4096
#define DMODEL 512
#define NHEADS 8
#define HDIM  64
#define ROWS  (BATCH * SEQ)
#define QKVCOLS (3 * DMODEL)

static __device__ float g_qkv[ROWS * QKVCOLS];
static __device__ float g_attn[ROWS * DMODEL];

__device__ __forceinline__ unsigned f2tf(float x) {
    unsigned r;
    asm("cvt.rna.tf32.f32 %0, %1;" : "=r"(r) : "f"(x));
    return r;
}

__device__ __forceinline__ void mma8(float* c,
                                     unsigned a0, unsigned a1, unsigned a2, unsigned a3,
                                     unsigned b0, unsigned b1) {
    asm("mma.sync.aligned.m16n8k8.row.col.f32.tf32.tf32.f32 "
        "{%0,%1,%2,%3}, {%4,%5,%6,%7}, {%8,%9}, {%0,%1,%2,%3};"
        : "+f"(c[0]), "+f"(c[1]), "+f"(c[2]), "+f"(c[3])
        : "r"(a0), "r"(a1), "r"(a2), "r"(a3), "r"(b0), "r"(b1));
}

// ---------------------------------------------------------------------------
// TF32 GEMM (R2 verbatim): C[M,N] = A[M,K] @ B[N,K]^T. Block 128x128,
// 128 threads (4 warps), warp tile 64x64, BK=32, pitch 36 (conflict-free).
// ---------------------------------------------------------------------------
#define GP 36

__global__ __launch_bounds__(128)
void gemm_tf32(const float* __restrict__ A, const float* __restrict__ B,
               float* __restrict__ C, int K, int N)
{
    __shared__ unsigned As[128 * GP];
    __shared__ unsigned Bs[128 * GP];

    const int tid  = threadIdx.x;
    const int lane = tid & 31;
    const int wid  = tid >> 5;
    const int g    = lane >> 2;
    const int cc   = lane & 3;
    const int wm   = (wid & 1) * 64;
    const int wn   = (wid >> 1) * 64;
    const int m0   = blockIdx.y * 128;
    const int n0   = blockIdx.x * 128;

    float acc[4][8][4];
    #pragma unroll
    for (int mt = 0; mt < 4; mt++)
        #pragma unroll
        for (int nt = 0; nt < 8; nt++)
            #pragma unroll
            for (int j = 0; j < 4; j++) acc[mt][nt][j] = 0.f;

    for (int k0 = 0; k0 < K; k0 += 32) {
        __syncthreads();
        #pragma unroll
        for (int i = 0; i < 8; i++) {
            int idx = i * 128 + tid;
            int r   = idx >> 3;
            int c4  = (idx & 7) << 2;
            float4 av = *(const float4*)(A + (size_t)(m0 + r) * K + k0 + c4);
            *(uint4*)&As[r * GP + c4] =
                make_uint4(f2tf(av.x), f2tf(av.y), f2tf(av.z), f2tf(av.w));
            float4 bv = *(const float4*)(B + (size_t)(n0 + r) * K + k0 + c4);
            *(uint4*)&Bs[r * GP + c4] =
                make_uint4(f2tf(bv.x), f2tf(bv.y), f2tf(bv.z), f2tf(bv.w));
        }
        __syncthreads();

        #pragma unroll
        for (int ks = 0; ks < 4; ks++) {
            unsigned a[4][4], b[8][2];
            #pragma unroll
            for (int mt = 0; mt < 4; mt++) {
                const unsigned* p = &As[(wm + mt * 16) * GP + ks * 8];
                a[mt][0] = p[g * GP + cc];
                a[mt][1] = p[(g + 8) * GP + cc];
                a[mt][2] = p[g * GP + cc + 4];
                a[mt][3] = p[(g + 8) * GP + cc + 4];
            }
            #pragma unroll
            for (int nt = 0; nt < 8; nt++) {
                const unsigned* p = &Bs[(wn + nt * 8 + g) * GP + ks * 8];
                b[nt][0] = p[cc];
                b[nt][1] = p[cc + 4];
            }
            #pragma unroll
            for (int mt = 0; mt < 4; mt++)
                #pragma unroll
                for (int nt = 0; nt < 8; nt++)
                    mma8(acc[mt][nt], a[mt][0], a[mt][1], a[mt][2], a[mt][3],
                         b[nt][0], b[nt][1]);
        }
    }

    #pragma unroll
    for (int mt = 0; mt < 4; mt++) {
        int row = m0 + wm + mt * 16 + g;
        #pragma unroll
        for (int nt = 0; nt < 8; nt++) {
            int col = n0 + wn + nt * 8 + 2 * cc;
            *(float2*)&C[(size_t)row * N + col] =
                make_float2(acc[mt][nt][0], acc[mt][nt][1]);
            *(float2*)&C[(size_t)(row + 8) * N + col] =
                make_float2(acc[mt][nt][2], acc[mt][nt][3]);
        }
    }
}

// ---------------------------------------------------------------------------
// TF32 flash attention, causal. R2 structure (128 threads, q-tile 64,
// pitch 72) + double-buffered K/V with register prefetch, 1 barrier/iter.
// ---------------------------------------------------------------------------
#define AP 72
#define ASMEM (6 * 64 * AP * 4)

__global__ __launch_bounds__(128)
void flash_tf32(const float* __restrict__ qkv, float* __restrict__ out)
{
    extern __shared__ unsigned sm[];
    unsigned* Qs  = sm;
    unsigned* Kb0 = Qs  + 64 * AP;
    unsigned* Kb1 = Kb0 + 64 * AP;
    unsigned* Vb0 = Kb1 + 64 * AP;
    unsigned* Vb1 = Vb0 + 64 * AP;
    unsigned* Ps  = Vb1 + 64 * AP;

    const int tid  = threadIdx.x;
    const int lane = tid & 31;
    const int w    = tid >> 5;
    const int g    = lane >> 2;
    const int cc   = lane & 3;
    const int qt   = (int)gridDim.x - 1 - (int)blockIdx.x;  // heavy tiles first
    const int b    = blockIdx.y >> 3;
    const int h    = blockIdx.y & 7;
    const int q0   = qt * 64;
    const size_t base = (size_t)b * SEQ * QKVCOLS + (size_t)h * HDIM;

    // ---- stage Q tile (pre-scaled by 1/8, tf32) ----
    #pragma unroll
    for (int i = 0; i < 8; i++) {
        int idx = i * 128 + tid;
        int r   = idx >> 4;
        int c4  = (idx & 15) << 2;
        float4 v = *(const float4*)(qkv + base + (size_t)(q0 + r) * QKVCOLS + c4);
        *(uint4*)&Qs[r * AP + c4] = make_uint4(
            f2tf(v.x * 0.125f), f2tf(v.y * 0.125f),
            f2tf(v.z * 0.125f), f2tf(v.w * 0.125f));
    }

    // ---- prologue: stage K/V tile 0 into buffer 0 ----
    {
        float4 kreg[8], vreg[8];
        #pragma unroll
        for (int i = 0; i < 8; i++) {
            int idx = i * 128 + tid;
            int r   = idx >> 4;
            int c4  = (idx & 15) << 2;
            const float* kp = qkv + base + (size_t)r * QKVCOLS + DMODEL + c4;
            kreg[i] = *(const float4*)kp;
            vreg[i] = *(const float4*)(kp + DMODEL);
        }
        #pragma unroll
        for (int i = 0; i < 8; i++) {
            int idx = i * 128 + tid;
            int r   = idx >> 4;
            int c4  = (idx & 15) << 2;
            *(uint4*)&Kb0[r * AP + c4] = make_uint4(
                f2tf(kreg[i].x), f2tf(kreg[i].y), f2tf(kreg[i].z), f2tf(kreg[i].w));
            *(uint4*)&Vb0[r * AP + c4] = make_uint4(
                f2tf(vreg[i].x), f2tf(vreg[i].y), f2tf(vreg[i].z), f2tf(vreg[i].w));
        }
    }
    __syncthreads();

    float rmax[2] = {-1e30f, -1e30f};
    float rsum[2] = {0.f, 0.f};
    float o[8][4];
    #pragma unroll
    for (int nt = 0; nt < 8; nt++)
        #pragma unroll
        for (int j = 0; j < 4; j++) o[nt][j] = 0.f;

    const int ntk = qt + 1;
    for (int kt = 0; kt < ntk; kt++) {
        const int k0 = kt * 64;
        unsigned* Kc = (kt & 1) ? Kb1 : Kb0;
        unsigned* Vc = (kt & 1) ? Vb1 : Vb0;
        unsigned* Kn = (kt & 1) ? Kb0 : Kb1;
        unsigned* Vn = (kt & 1) ? Vb0 : Vb1;
        const bool pf = (kt + 1 < ntk);
        const int k0n = k0 + 64;

        // ---- prefetch next K tile into registers (overlaps S-MMA) ----
        float4 kreg[8];
        if (pf) {
            #pragma unroll
            for (int i = 0; i < 8; i++) {
                int idx = i * 128 + tid;
                int r   = idx >> 4;
                int c4  = (idx & 15) << 2;
                kreg[i] = *(const float4*)(qkv + base +
                            (size_t)(k0n + r) * QKVCOLS + DMODEL + c4);
            }
        }

        // ---- S = Q @ K^T  (warp: 16 x 64) ----
        float s[8][4];
        #pragma unroll
        for (int nt = 0; nt < 8; nt++)
            #pragma unroll
            for (int j = 0; j < 4; j++) s[nt][j] = 0.f;

        #pragma unroll
        for (int ks = 0; ks < 8; ks++) {
            const unsigned* qp = &Qs[(w * 16) * AP + ks * 8];
            unsigned a0 = qp[g * AP + cc];
            unsigned a1 = qp[(g + 8) * AP + cc];
            unsigned a2 = qp[g * AP + cc + 4];
            unsigned a3 = qp[(g + 8) * AP + cc + 4];
            #pragma unroll
            for (int nt = 0; nt < 8; nt++) {
                const unsigned* kp2 = &Kc[(nt * 8 + g) * AP + ks * 8];
                mma8(s[nt], a0, a1, a2, a3, kp2[cc], kp2[cc + 4]);
            }
        }

        // ---- causal mask (diagonal tile only) ----
        if (kt == ntk - 1) {
            #pragma unroll
            for (int nt = 0; nt < 8; nt++) {
                int col = k0 + nt * 8 + 2 * cc;
                int r0  = q0 + w * 16 + g;
                int r1  = r0 + 8;
                if (col     > r0) s[nt][0] = -1e30f;
                if (col + 1 > r0) s[nt][1] = -1e30f;
                if (col     > r1) s[nt][2] = -1e30f;
                if (col + 1 > r1) s[nt][3] = -1e30f;
            }
        }

        // ---- online softmax (rows g, g+8) ----
        #pragma unroll
        for (int half = 0; half < 2; half++) {
            float mx = -1e30f;
            #pragma unroll
            for (int nt = 0; nt < 8; nt++)
                mx = fmaxf(mx, fmaxf(s[nt][half * 2], s[nt][half * 2 + 1]));
            mx = fmaxf(mx, __shfl_xor_sync(0xffffffffu, mx, 1));
            mx = fmaxf(mx, __shfl_xor_sync(0xffffffffu, mx, 2));
            const float nm   = fmaxf(rmax[half], mx);
            const float corr = __expf(rmax[half] - nm);
            rmax[half] = nm;

            float sum = 0.f;
            unsigned* pr = &Ps[(w * 16 + g + half * 8) * AP];
            #pragma unroll
            for (int nt = 0; nt < 8; nt++) {
                float p0 = __expf(s[nt][half * 2]     - nm);
                float p1 = __expf(s[nt][half * 2 + 1] - nm);
                sum += p0 + p1;
                *(uint2*)&pr[nt * 8 + 2 * cc] = make_uint2(f2tf(p0), f2tf(p1));
                o[nt][half * 2]     *= corr;
                o[nt][half * 2 + 1] *= corr;
            }
            sum += __shfl_xor_sync(0xffffffffu, sum, 1);
            sum += __shfl_xor_sync(0xffffffffu, sum, 2);
            rsum[half] = rsum[half] * corr + sum;
        }
        __syncwarp();   // P STS -> P LDS within warp

        // ---- store prefetched K into next buffer ----
        if (pf) {
            #pragma unroll
            for (int i = 0; i < 8; i++) {
                int idx = i * 128 + tid;
                int r   = idx >> 4;
                int c4  = (idx & 15) << 2;
                *(uint4*)&Kn[r * AP + c4] = make_uint4(
                    f2tf(kreg[i].x), f2tf(kreg[i].y),
                    f2tf(kreg[i].z), f2tf(kreg[i].w));
            }
        }

        // ---- prefetch next V tile (overlaps PV-MMA) ----
        float4 vreg[8];
        if (pf) {
            #pragma unroll
            for (int i = 0; i < 8; i++) {
                int idx = i * 128 + tid;
                int r   = idx >> 4;
                int c4  = (idx & 15) << 2;
                vreg[i] = *(const float4*)(qkv + base +
                            (size_t)(k0n + r) * QKVCOLS + 2 * DMODEL + c4);
            }
        }

        // ---- O += P @ V ----
        #pragma unroll
        for (int ks = 0; ks < 8; ks++) {
            const unsigned* pp = &Ps[(w * 16) * AP + ks * 8];
            unsigned a0 = pp[g * AP + cc];
            unsigned a1 = pp[(g + 8) * AP + cc];
            unsigned a2 = pp[g * AP + cc + 4];
            unsigned a3 = pp[(g + 8) * AP + cc + 4];
            #pragma unroll
            for (int nt = 0; nt < 8; nt++) {
                const unsigned* vp = &Vc[(ks * 8) * AP + nt * 8 + g];
                mma8(o[nt], a0, a1, a2, a3, vp[cc * AP], vp[(cc + 4) * AP]);
            }
        }

        // ---- store prefetched V into next buffer ----
        if (pf) {
            #pragma unroll
            for (int i = 0; i < 8; i++) {
                int idx = i * 128 + tid;
                int r   = idx >> 4;
                int c4  = (idx & 15) << 2;
                *(uint4*)&Vn[r * AP + c4] = make_uint4(
                    f2tf(vreg[i].x), f2tf(vreg[i].y),
                    f2tf(vreg[i].z), f2tf(vreg[i].w));
            }
        }

        __syncthreads();   // next buffers ready; current buffers free
    }

    // ---- epilogue: normalize, store to [B,T,512] ----
    const float inv0 = 1.f / rsum[0];
    const float inv1 = 1.f / rsum[1];
    const size_t orow = (size_t)b * SEQ + q0 + w * 16 + g;
    #pragma unroll
    for (int nt = 0; nt < 8; nt++) {
        size_t off = orow * DMODEL + h * HDIM + nt * 8 + 2 * cc;
        *(float2*)&out[off] = make_float2(o[nt][0] * inv0, o[nt][1] * inv0);
        *(float2*)&out[off + 8 * DMODEL] = make_float2(o[nt][2] * inv1, o[nt][3] * inv1);
    }
}

// ---------------------------------------------------------------------------
extern "C" void kernel_launch(void* const* d_in, const int* in_sizes, int n_in,
                              void* d_out, int out_size)
{
    const float* x    = (const float*)d_in[0];
    const float* wqkv = (const float*)d_in[1];
    const float* wo   = (const float*)d_in[2];
    float* out        = (float*)d_out;

    float *qkvp, *attnp;
    cudaGetSymbolAddress((void**)&qkvp, g_qkv);
    cudaGetSymbolAddress((void**)&attnp, g_attn);

    cudaFuncSetAttribute(flash_tf32,
                         cudaFuncAttributeMaxDynamicSharedMemorySize, ASMEM);

    // qkv = x @ W_QKV^T : M=8192, N=1536, K=512
    gemm_tf32<<<dim3(QKVCOLS / 128, ROWS / 128), 128>>>(x, wqkv, qkvp, DMODEL, QKVCOLS);

    // causal flash attention
    flash_tf32<<<dim3(SEQ / 64, BATCH * NHEADS), 128, ASMEM>>>(qkvp, attnp);

    // y = attn @ W_O^T : M=8192, N=512, K=512
    gemm_tf32<<<dim3(DMODEL / 128, ROWS / 128), 128>>>(attnp, wo, out, DMODEL, DMODEL);
}

// round 6
// speedup vs baseline: 2.0526x; 1.2155x over previous
#include <cuda_runtime.h>
#include <math.h>

// ---------------------------------------------------------------------------
// CausalSelfAttention via TF32 tensor-core mma.sync (sm_103a)
// GEMMs: R2-verbatim (known-good 95us). Flash: q-tile 128, 4 warps x 32 rows,
// single-buffered K/V, pitch-72 scalar fragment layout (R2-proven banks).
// ---------------------------------------------------------------------------

#define BATCH 2
#define SEQ   4096
#define DMODEL 512
#define NHEADS 8
#define HDIM  64
#define ROWS  (BATCH * SEQ)
#define QKVCOLS (3 * DMODEL)

static __device__ float g_qkv[ROWS * QKVCOLS];
static __device__ float g_attn[ROWS * DMODEL];

__device__ __forceinline__ unsigned f2tf(float x) {
    unsigned r;
    asm("cvt.rna.tf32.f32 %0, %1;" : "=r"(r) : "f"(x));
    return r;
}

__device__ __forceinline__ void mma8(float* c,
                                     unsigned a0, unsigned a1, unsigned a2, unsigned a3,
                                     unsigned b0, unsigned b1) {
    asm("mma.sync.aligned.m16n8k8.row.col.f32.tf32.tf32.f32 "
        "{%0,%1,%2,%3}, {%4,%5,%6,%7}, {%8,%9}, {%0,%1,%2,%3};"
        : "+f"(c[0]), "+f"(c[1]), "+f"(c[2]), "+f"(c[3])
        : "r"(a0), "r"(a1), "r"(a2), "r"(a3), "r"(b0), "r"(b1));
}

// ---------------------------------------------------------------------------
// TF32 GEMM (R2 verbatim): C[M,N] = A[M,K] @ B[N,K]^T. Block 128x128,
// 128 threads (4 warps), warp tile 64x64, BK=32, pitch 36 (conflict-free).
// ---------------------------------------------------------------------------
#define GP 36

__global__ __launch_bounds__(128)
void gemm_tf32(const float* __restrict__ A, const float* __restrict__ B,
               float* __restrict__ C, int K, int N)
{
    __shared__ unsigned As[128 * GP];
    __shared__ unsigned Bs[128 * GP];

    const int tid  = threadIdx.x;
    const int lane = tid & 31;
    const int wid  = tid >> 5;
    const int g    = lane >> 2;
    const int cc   = lane & 3;
    const int wm   = (wid & 1) * 64;
    const int wn   = (wid >> 1) * 64;
    const int m0   = blockIdx.y * 128;
    const int n0   = blockIdx.x * 128;

    float acc[4][8][4];
    #pragma unroll
    for (int mt = 0; mt < 4; mt++)
        #pragma unroll
        for (int nt = 0; nt < 8; nt++)
            #pragma unroll
            for (int j = 0; j < 4; j++) acc[mt][nt][j] = 0.f;

    for (int k0 = 0; k0 < K; k0 += 32) {
        __syncthreads();
        #pragma unroll
        for (int i = 0; i < 8; i++) {
            int idx = i * 128 + tid;
            int r   = idx >> 3;
            int c4  = (idx & 7) << 2;
            float4 av = *(const float4*)(A + (size_t)(m0 + r) * K + k0 + c4);
            *(uint4*)&As[r * GP + c4] =
                make_uint4(f2tf(av.x), f2tf(av.y), f2tf(av.z), f2tf(av.w));
            float4 bv = *(const float4*)(B + (size_t)(n0 + r) * K + k0 + c4);
            *(uint4*)&Bs[r * GP + c4] =
                make_uint4(f2tf(bv.x), f2tf(bv.y), f2tf(bv.z), f2tf(bv.w));
        }
        __syncthreads();

        #pragma unroll
        for (int ks = 0; ks < 4; ks++) {
            unsigned a[4][4], b[8][2];
            #pragma unroll
            for (int mt = 0; mt < 4; mt++) {
                const unsigned* p = &As[(wm + mt * 16) * GP + ks * 8];
                a[mt][0] = p[g * GP + cc];
                a[mt][1] = p[(g + 8) * GP + cc];
                a[mt][2] = p[g * GP + cc + 4];
                a[mt][3] = p[(g + 8) * GP + cc + 4];
            }
            #pragma unroll
            for (int nt = 0; nt < 8; nt++) {
                const unsigned* p = &Bs[(wn + nt * 8 + g) * GP + ks * 8];
                b[nt][0] = p[cc];
                b[nt][1] = p[cc + 4];
            }
            #pragma unroll
            for (int mt = 0; mt < 4; mt++)
                #pragma unroll
                for (int nt = 0; nt < 8; nt++)
                    mma8(acc[mt][nt], a[mt][0], a[mt][1], a[mt][2], a[mt][3],
                         b[nt][0], b[nt][1]);
        }
    }

    #pragma unroll
    for (int mt = 0; mt < 4; mt++) {
        int row = m0 + wm + mt * 16 + g;
        #pragma unroll
        for (int nt = 0; nt < 8; nt++) {
            int col = n0 + wn + nt * 8 + 2 * cc;
            *(float2*)&C[(size_t)row * N + col] =
                make_float2(acc[mt][nt][0], acc[mt][nt][1]);
            *(float2*)&C[(size_t)(row + 8) * N + col] =
                make_float2(acc[mt][nt][2], acc[mt][nt][3]);
        }
    }
}

// ---------------------------------------------------------------------------
// TF32 flash attention, causal. 128 threads (4 warps), q-tile 128 (32 q-rows
// per warp, 2 m16 blocks), kv-tile 64, pitch 72, single-buffered K/V.
// ---------------------------------------------------------------------------
#define AP 72
#define ASMEM ((128 + 64 + 64 + 128) * AP * 4)

__global__ __launch_bounds__(128)
void flash_tf32(const float* __restrict__ qkv, float* __restrict__ out)
{
    extern __shared__ unsigned sm[];
    unsigned* Qs = sm;                 // 128 x AP
    unsigned* Ks = Qs + 128 * AP;      // 64 x AP
    unsigned* Vs = Ks + 64 * AP;       // 64 x AP (row-major [kv][d])
    unsigned* Ps = Vs + 64 * AP;       // 128 x AP

    const int tid  = threadIdx.x;
    const int lane = tid & 31;
    const int w    = tid >> 5;
    const int g    = lane >> 2;
    const int cc   = lane & 3;
    const int qt   = (int)gridDim.x - 1 - (int)blockIdx.x;  // heavy tiles first
    const int b    = blockIdx.y >> 3;
    const int h    = blockIdx.y & 7;
    const int q0   = qt * 128;
    const int wrow = w * 32;           // warp's first q-row within tile
    const size_t base = (size_t)b * SEQ * QKVCOLS + (size_t)h * HDIM;

    // ---- stage Q tile (128 x 64, pre-scaled by 1/8, tf32) ----
    #pragma unroll
    for (int i = 0; i < 16; i++) {
        int idx = i * 128 + tid;
        int r   = idx >> 4;
        int c4  = (idx & 15) << 2;
        float4 v = *(const float4*)(qkv + base + (size_t)(q0 + r) * QKVCOLS + c4);
        *(uint4*)&Qs[r * AP + c4] = make_uint4(
            f2tf(v.x * 0.125f), f2tf(v.y * 0.125f),
            f2tf(v.z * 0.125f), f2tf(v.w * 0.125f));
    }

    float rmax[2][2], rsum[2][2];
    float o[2][8][4];
    #pragma unroll
    for (int mt = 0; mt < 2; mt++) {
        rmax[mt][0] = rmax[mt][1] = -1e30f;
        rsum[mt][0] = rsum[mt][1] = 0.f;
        #pragma unroll
        for (int nt = 0; nt < 8; nt++)
            #pragma unroll
            for (int j = 0; j < 4; j++) o[mt][nt][j] = 0.f;
    }

    const int ntk = 2 * qt + 2;
    for (int kt = 0; kt < ntk; kt++) {
        const int k0 = kt * 64;
        __syncthreads();   // previous Ks/Vs fully consumed

        // ---- stage K, V tiles (64 x 64 each, coalesced) ----
        #pragma unroll
        for (int i = 0; i < 8; i++) {
            int idx = i * 128 + tid;
            int r   = idx >> 4;
            int c4  = (idx & 15) << 2;
            const float* kp = qkv + base + (size_t)(k0 + r) * QKVCOLS + DMODEL + c4;
            float4 kv = *(const float4*)kp;
            float4 vv = *(const float4*)(kp + DMODEL);
            *(uint4*)&Ks[r * AP + c4] =
                make_uint4(f2tf(kv.x), f2tf(kv.y), f2tf(kv.z), f2tf(kv.w));
            *(uint4*)&Vs[r * AP + c4] =
                make_uint4(f2tf(vv.x), f2tf(vv.y), f2tf(vv.z), f2tf(vv.w));
        }
        __syncthreads();

        // warp skips kv tiles entirely above its rows (fully masked)
        if (k0 > q0 + wrow + 31) continue;

        // ---- S = Q @ K^T  (warp: 32 q-rows x 64 kv) ----
        float s[2][8][4];
        #pragma unroll
        for (int mt = 0; mt < 2; mt++)
            #pragma unroll
            for (int nt = 0; nt < 8; nt++)
                #pragma unroll
                for (int j = 0; j < 4; j++) s[mt][nt][j] = 0.f;

        #pragma unroll
        for (int ks = 0; ks < 8; ks++) {
            unsigned a[2][4];
            #pragma unroll
            for (int mt = 0; mt < 2; mt++) {
                const unsigned* qp = &Qs[(wrow + mt * 16) * AP + ks * 8];
                a[mt][0] = qp[g * AP + cc];
                a[mt][1] = qp[(g + 8) * AP + cc];
                a[mt][2] = qp[g * AP + cc + 4];
                a[mt][3] = qp[(g + 8) * AP + cc + 4];
            }
            #pragma unroll
            for (int nt = 0; nt < 8; nt++) {
                const unsigned* kp2 = &Ks[(nt * 8 + g) * AP + ks * 8];
                unsigned b0 = kp2[cc];
                unsigned b1 = kp2[cc + 4];
                #pragma unroll
                for (int mt = 0; mt < 2; mt++)
                    mma8(s[mt][nt], a[mt][0], a[mt][1], a[mt][2], a[mt][3], b0, b1);
            }
        }

        // ---- causal mask (diagonal band tiles only) ----
        #pragma unroll
        for (int mt = 0; mt < 2; mt++) {
            if (k0 + 63 > q0 + wrow + mt * 16) {
                const int r0 = q0 + wrow + mt * 16 + g;
                const int r1 = r0 + 8;
                #pragma unroll
                for (int nt = 0; nt < 8; nt++) {
                    int col = k0 + nt * 8 + 2 * cc;
                    if (col     > r0) s[mt][nt][0] = -1e30f;
                    if (col + 1 > r0) s[mt][nt][1] = -1e30f;
                    if (col     > r1) s[mt][nt][2] = -1e30f;
                    if (col + 1 > r1) s[mt][nt][3] = -1e30f;
                }
            }
        }

        // ---- online softmax (per mt block: rows g, g+8) ----
        #pragma unroll
        for (int mt = 0; mt < 2; mt++) {
            #pragma unroll
            for (int half = 0; half < 2; half++) {
                float mx = -1e30f;
                #pragma unroll
                for (int nt = 0; nt < 8; nt++)
                    mx = fmaxf(mx, fmaxf(s[mt][nt][half * 2], s[mt][nt][half * 2 + 1]));
                mx = fmaxf(mx, __shfl_xor_sync(0xffffffffu, mx, 1));
                mx = fmaxf(mx, __shfl_xor_sync(0xffffffffu, mx, 2));
                const float nm   = fmaxf(rmax[mt][half], mx);
                const float corr = __expf(rmax[mt][half] - nm);
                rmax[mt][half] = nm;

                float sum = 0.f;
                unsigned* pr = &Ps[(wrow + mt * 16 + g + half * 8) * AP];
                #pragma unroll
                for (int nt = 0; nt < 8; nt++) {
                    float p0 = __expf(s[mt][nt][half * 2]     - nm);
                    float p1 = __expf(s[mt][nt][half * 2 + 1] - nm);
                    sum += p0 + p1;
                    *(uint2*)&pr[nt * 8 + 2 * cc] = make_uint2(f2tf(p0), f2tf(p1));
                    o[mt][nt][half * 2]     *= corr;
                    o[mt][nt][half * 2 + 1] *= corr;
                }
                sum += __shfl_xor_sync(0xffffffffu, sum, 1);
                sum += __shfl_xor_sync(0xffffffffu, sum, 2);
                rsum[mt][half] = rsum[mt][half] * corr + sum;
            }
        }
        __syncwarp();   // P rows are warp-private

        // ---- O += P @ V ----
        #pragma unroll
        for (int ks = 0; ks < 8; ks++) {
            unsigned a[2][4];
            #pragma unroll
            for (int mt = 0; mt < 2; mt++) {
                const unsigned* pp = &Ps[(wrow + mt * 16) * AP + ks * 8];
                a[mt][0] = pp[g * AP + cc];
                a[mt][1] = pp[(g + 8) * AP + cc];
                a[mt][2] = pp[g * AP + cc + 4];
                a[mt][3] = pp[(g + 8) * AP + cc + 4];
            }
            #pragma unroll
            for (int nt = 0; nt < 8; nt++) {
                const unsigned* vp = &Vs[(ks * 8) * AP + nt * 8 + g];
                unsigned b0 = vp[cc * AP];
                unsigned b1 = vp[(cc + 4) * AP];
                #pragma unroll
                for (int mt = 0; mt < 2; mt++)
                    mma8(o[mt][nt], a[mt][0], a[mt][1], a[mt][2], a[mt][3], b0, b1);
            }
        }
    }

    // ---- epilogue: normalize, store to [B,T,512] ----
    #pragma unroll
    for (int mt = 0; mt < 2; mt++) {
        const float inv0 = 1.f / rsum[mt][0];
        const float inv1 = 1.f / rsum[mt][1];
        const size_t orow = (size_t)b * SEQ + q0 + wrow + mt * 16 + g;
        #pragma unroll
        for (int nt = 0; nt < 8; nt++) {
            size_t off = orow * DMODEL + h * HDIM + nt * 8 + 2 * cc;
            *(float2*)&out[off] =
                make_float2(o[mt][nt][0] * inv0, o[mt][nt][1] * inv0);
            *(float2*)&out[off + 8 * DMODEL] =
                make_float2(o[mt][nt][2] * inv1, o[mt][nt][3] * inv1);
        }
    }
}

// ---------------------------------------------------------------------------
extern "C" void kernel_launch(void* const* d_in, const int* in_sizes, int n_in,
                              void* d_out, int out_size)
{
    const float* x    = (const float*)d_in[0];
    const float* wqkv = (const float*)d_in[1];
    const float* wo   = (const float*)d_in[2];
    float* out        = (float*)d_out;

    float *qkvp, *attnp;
    cudaGetSymbolAddress((void**)&qkvp, g_qkv);
    cudaGetSymbolAddress((void**)&attnp, g_attn);

    cudaFuncSetAttribute(flash_tf32,
                         cudaFuncAttributeMaxDynamicSharedMemorySize, ASMEM);

    // qkv = x @ W_QKV^T : M=8192, N=1536, K=512
    gemm_tf32<<<dim3(QKVCOLS / 128, ROWS / 128), 128>>>(x, wqkv, qkvp, DMODEL, QKVCOLS);

    // causal flash attention (q-tile 128, 4 warps x 32 rows)
    flash_tf32<<<dim3(SEQ / 128, BATCH * NHEADS), 128, ASMEM>>>(qkvp, attnp);

    // y = attn @ W_O^T : M=8192, N=512, K=512
    gemm_tf32<<<dim3(DMODEL / 128, ROWS / 128), 128>>>(attnp, wo, out, DMODEL, DMODEL);
}